// round 3
// baseline (speedup 1.0000x reference)
#include <cuda_runtime.h>
#include <cuda_bf16.h>
#include <mma.h>
#include <cmath>

using namespace nvcuda;

// ---------------- problem constants ----------------
#define NWIN   8192
#define TTOK   401408
#define HWI    224
#define HWSQ   50176
#define DIMC   192

__device__ __forceinline__ float tf32r(float v) {
    float r;
    asm("cvt.rna.tf32.f32 %0, %1;" : "=f"(r) : "f"(v));
    return r;
}

// scratch (allocation-free static device arrays)
__device__ float g_h1  [(size_t)TTOK * DIMC];   // x + attn branch (fp32)
__device__ float g_h1n [(size_t)TTOK * DIMC];   // LN2(h1), tf32-rounded
__device__ float g_qkvw_t[192 * 576];           // tf32-rounded weights
__device__ float g_projw_t[192 * 192];
__device__ float g_fc1w_t [192 * 768];
__device__ float g_fc2w_t [768 * 192];
__device__ float g_bias   [6 * 49 * 49];        // rpb[relidx[r,j]*6+h]

typedef wmma::fragment<wmma::matrix_a,16,16,8,wmma::precision::tf32,wmma::row_major> FragA;
typedef wmma::fragment<wmma::matrix_b,16,16,8,wmma::precision::tf32,wmma::row_major> FragB;
typedef wmma::fragment<wmma::matrix_b,16,16,8,wmma::precision::tf32,wmma::col_major> FragBT;
typedef wmma::fragment<wmma::accumulator,16,16,8,float> FragC;

// ---------------- prelude: tf32-round weights + bias table ----------------
#define W_QKV 110592
#define W_PRJ  36864
#define W_FC1 147456
#define W_FC2 147456
#define N_BIAS 14406   // 6*49*49
#define PRE_TOT (W_QKV + W_PRJ + W_FC1 + W_FC2 + N_BIAS)

__global__ void prelude(const float* __restrict__ qkvw, const float* __restrict__ projw,
                        const float* __restrict__ fc1w, const float* __restrict__ fc2w,
                        const float* __restrict__ rpb,  const int* __restrict__ relidx)
{
    int i = blockIdx.x * blockDim.x + threadIdx.x;
    if (i < W_QKV) { g_qkvw_t[i] = tf32r(qkvw[i]); return; }
    i -= W_QKV;
    if (i < W_PRJ) { g_projw_t[i] = tf32r(projw[i]); return; }
    i -= W_PRJ;
    if (i < W_FC1) { g_fc1w_t[i] = tf32r(fc1w[i]); return; }
    i -= W_FC1;
    if (i < W_FC2) { g_fc2w_t[i] = tf32r(fc2w[i]); return; }
    i -= W_FC2;
    if (i < N_BIAS) {
        int h = i / 2401, rj = i - h * 2401;
        g_bias[i] = rpb[relidx[rj] * 6 + h];
    }
}

// ============================================================================
// Kernel 1: per-window (512 threads, 16 warps)
// smem (floats):
//   xs  [64][196] @0       : LN1 out (tf32) -> attn out -> proj A (tf32)
//   qkv [64][580] @12544   : QKV (q scaled+biased, tf32) ; later proj out fp32
//   sc  [64][68]  @49664   : per-head scores -> probs (tf32, in place)
// total floats 54016 -> 216,064 bytes
// ============================================================================
#define XS_LD 196
#define QK_LD 580
#define SC_LD 68
#define ATTN_SMEM 216064

__global__ void __launch_bounds__(512, 1)
attn_kernel(const float* __restrict__ x,
            const float* __restrict__ ln1w, const float* __restrict__ ln1b,
            const float* __restrict__ qkvb,
            const float* __restrict__ projb,
            const float* __restrict__ ln2w, const float* __restrict__ ln2b)
{
    extern __shared__ float sm[];
    float* xs  = sm;
    float* qkv = sm + 12544;
    float* sc  = sm + 49664;

    const int tid  = threadIdx.x;
    const int wid  = tid >> 5;
    const int lane = tid & 31;

    const int win = blockIdx.x;
    const int b   = win >> 10;
    const int wh  = (win >> 5) & 31;
    const int ww  = win & 31;
    const float* xb = x + (size_t)b * DIMC * HWSQ;

    // zero pad rows of xs (rows 49..63)
    for (int i = 49 * XS_LD + tid; i < 64 * XS_LD; i += 512) xs[i] = 0.f;
    // gather window
    for (int idx = tid; idx < DIMC * 49; idx += 512) {
        int c = idx / 49, r = idx - c * 49;
        int i = r / 7, j = r - i * 7;
        xs[r * XS_LD + c] = xb[(size_t)c * HWSQ + (wh * 7 + i) * HWI + (ww * 7 + j)];
    }
    __syncthreads();

    // LN1 -> tf32-rounded
    for (int r = wid; r < 49; r += 16) {
        float v[6]; float s = 0.f;
#pragma unroll
        for (int q = 0; q < 6; q++) { v[q] = xs[r * XS_LD + lane + q * 32]; s += v[q]; }
#pragma unroll
        for (int o = 16; o; o >>= 1) s += __shfl_xor_sync(~0u, s, o);
        float mu = s * (1.f / 192.f);
        float vs = 0.f;
#pragma unroll
        for (int q = 0; q < 6; q++) { float d = v[q] - mu; vs += d * d; }
#pragma unroll
        for (int o = 16; o; o >>= 1) vs += __shfl_xor_sync(~0u, vs, o);
        float rs = rsqrtf(vs * (1.f / 192.f) + 1e-5f);
#pragma unroll
        for (int q = 0; q < 6; q++) {
            int c = lane + q * 32;
            xs[r * XS_LD + c] = tf32r((v[q] - mu) * rs * ln1w[c] + ln1b[c]);
        }
    }
    __syncthreads();

    // ---- QKV GEMM [64,192]x[192,576] -> qkv (raw fp32) ----
    {
        const int rt = wid & 3, ctb = wid >> 2;
#pragma unroll
        for (int i = 0; i < 9; i++) {
            int ct = ctb + 4 * i;
            FragC acc; wmma::fill_fragment(acc, 0.f);
#pragma unroll
            for (int k = 0; k < 24; k++) {
                FragA af; wmma::load_matrix_sync(af, xs + rt * 16 * XS_LD + k * 8, XS_LD);
                FragB bf; wmma::load_matrix_sync(bf, g_qkvw_t + (size_t)k * 8 * 576 + ct * 16, 576);
                wmma::mma_sync(acc, af, bf, acc);
            }
            wmma::store_matrix_sync(qkv + rt * 16 * QK_LD + ct * 16, acc, QK_LD, wmma::mem_row_major);
        }
    }
    __syncthreads();
    // epilogue: bias, scale q, tf32-round (rows<49 only; pad rows are exactly 0)
    const float scale = 0.17677669529663687f;
    for (int idx = tid; idx < 49 * 576; idx += 512) {
        int r = idx / 576, c = idx - r * 576;
        float v = qkv[r * QK_LD + c] + qkvb[c];
        if (c < 192) v *= scale;
        qkv[r * QK_LD + c] = tf32r(v);
    }
    __syncthreads();

    // ---- attention: one head per iteration (16 warps) ----
    for (int h = 0; h < 6; h++) {
        // scores = Qs @ K^T : 16 tiles, one per warp
        {
            int rt = wid >> 2, ct = wid & 3;
            FragC acc; wmma::fill_fragment(acc, 0.f);
#pragma unroll
            for (int k = 0; k < 4; k++) {
                FragA af; wmma::load_matrix_sync(af, qkv + rt * 16 * QK_LD + h * 32 + k * 8, QK_LD);
                FragBT bf; wmma::load_matrix_sync(bf, qkv + ct * 16 * QK_LD + 192 + h * 32 + k * 8, QK_LD);
                wmma::mma_sync(acc, af, bf, acc);
            }
            wmma::store_matrix_sync(sc + rt * 16 * SC_LD + ct * 16, acc, SC_LD, wmma::mem_row_major);
        }
        __syncthreads();

        // softmax (+ precomputed bias) in place, tf32-rounded
        const float* bh = g_bias + h * 2401;
        for (int r = wid; r < 49; r += 16) {
            float* srow = sc + r * SC_LD;
            int j0 = lane, j1 = lane + 32;
            float v0 = srow[j0] + bh[r * 49 + j0];
            float v1 = (j1 < 49) ? srow[j1] + bh[r * 49 + j1] : -1e30f;
            float m = fmaxf(v0, v1);
#pragma unroll
            for (int o = 16; o; o >>= 1) m = fmaxf(m, __shfl_xor_sync(~0u, m, o));
            float e0 = expf(v0 - m);
            float e1 = (j1 < 49) ? expf(v1 - m) : 0.f;
            float s = e0 + e1;
#pragma unroll
            for (int o = 16; o; o >>= 1) s += __shfl_xor_sync(~0u, s, o);
            float inv = 1.f / s;
            srow[j0] = tf32r(e0 * inv);
            if (j1 < 49) srow[j1] = tf32r(e1 * inv);
        }
        __syncthreads();

        // PV: 8 tiles (warps 0..7) -> xs cols [h*32, h*32+32), raw fp32
        if (wid < 8) {
            int rt = wid >> 1, ct = wid & 1;
            FragC acc; wmma::fill_fragment(acc, 0.f);
#pragma unroll
            for (int k = 0; k < 8; k++) {
                FragA af; wmma::load_matrix_sync(af, sc + rt * 16 * SC_LD + k * 8, SC_LD);
                FragB bf; wmma::load_matrix_sync(bf, qkv + (size_t)k * 8 * QK_LD + 384 + h * 32 + ct * 16, QK_LD);
                wmma::mma_sync(acc, af, bf, acc);
            }
            wmma::store_matrix_sync(xs + rt * 16 * XS_LD + h * 32 + ct * 16, acc, XS_LD, wmma::mem_row_major);
        }
        __syncthreads();
    }

    // tf32-round attn output (proj A operand), rows<49 (pad rows stayed 0)
    for (int idx = tid; idx < 49 * 192; idx += 512) {
        int r = idx / 192, c = idx - r * 192;
        xs[r * XS_LD + c] = tf32r(xs[r * XS_LD + c]);
    }
    __syncthreads();

    // ---- proj GEMM: [64,192]x[192,192] -> qkv region (ld XS_LD) fp32 ----
    {
        const int rt = wid & 3, ctb = wid >> 2;
#pragma unroll
        for (int i = 0; i < 3; i++) {
            int ct = ctb + 4 * i;
            FragC acc; wmma::fill_fragment(acc, 0.f);
#pragma unroll
            for (int k = 0; k < 24; k++) {
                FragA af; wmma::load_matrix_sync(af, xs + rt * 16 * XS_LD + k * 8, XS_LD);
                FragB bf; wmma::load_matrix_sync(bf, g_projw_t + (size_t)k * 8 * 192 + ct * 16, 192);
                wmma::mma_sync(acc, af, bf, acc);
            }
            wmma::store_matrix_sync(qkv + rt * 16 * XS_LD + ct * 16, acc, XS_LD, wmma::mem_row_major);
        }
    }
    __syncthreads();

    // residual: qkv(ld XS_LD) += x + projb
    for (int idx = tid; idx < DIMC * 49; idx += 512) {
        int c = idx / 49, r = idx - c * 49;
        int i = r / 7, j = r - i * 7;
        float xv = xb[(size_t)c * HWSQ + (wh * 7 + i) * HWI + (ww * 7 + j)];
        qkv[r * XS_LD + c] += xv + projb[c];
    }
    __syncthreads();

    // LN2 + write h1 (fp32) / h1n (tf32-rounded fp32)
    size_t base = (size_t)win * 49 * DIMC;
    for (int r = wid; r < 49; r += 16) {
        float v[6]; float s = 0.f;
#pragma unroll
        for (int q = 0; q < 6; q++) { v[q] = qkv[r * XS_LD + lane + q * 32]; s += v[q]; }
#pragma unroll
        for (int o = 16; o; o >>= 1) s += __shfl_xor_sync(~0u, s, o);
        float mu = s * (1.f / 192.f);
        float vs = 0.f;
#pragma unroll
        for (int q = 0; q < 6; q++) { float d = v[q] - mu; vs += d * d; }
#pragma unroll
        for (int o = 16; o; o >>= 1) vs += __shfl_xor_sync(~0u, vs, o);
        float rs = rsqrtf(vs * (1.f / 192.f) + 1e-5f);
#pragma unroll
        for (int q = 0; q < 6; q++) {
            int c = lane + q * 32;
            g_h1 [base + r * DIMC + c] = v[q];
            g_h1n[base + r * DIMC + c] = tf32r((v[q] - mu) * rs * ln2w[c] + ln2b[c]);
        }
    }
}

// ============================================================================
// Kernel 2 (256 threads, 2 CTAs/SM): per 64-token tile, 4 K-chunks of 192,
// GEMM2 register-accumulated. smem: as f32[64][196] @0 ; mid f32[64][196]
// total (12544+12544)*4 = 100,352 bytes
// ============================================================================
#define MLP_SMEM 100352

__global__ void __launch_bounds__(256, 2)
mlp_kernel(const float* __restrict__ fc1b, const float* __restrict__ fc2b,
           float* __restrict__ out)
{
    extern __shared__ float sm[];
    float* as  = sm;
    float* mid = sm + 12544;

    const int tid = threadIdx.x;
    const int wid = tid >> 5;
    const int t0  = blockIdx.x * 64;
    const int rt  = wid & 3;
    const int ctb = wid >> 2;   // 0 or 1

    // load h1n tile (float4 coalesced)
    {
        const float4* src = (const float4*)g_h1n;
        float4* dst = (float4*)as;
        for (int idx = tid; idx < 64 * 48; idx += 256) {
            int r = idx / 48, c4 = idx - r * 48;
            dst[r * 49 + c4] = src[(size_t)(t0 + r) * 48 + c4];
        }
    }
    __syncthreads();

    FragC acc2[6];
#pragma unroll
    for (int j = 0; j < 6; j++) wmma::fill_fragment(acc2[j], 0.f);

    for (int chunk = 0; chunk < 4; chunk++) {
        // GEMM1: [64,192] x [192, 192-chunk] -> mid fp32
#pragma unroll
        for (int i = 0; i < 6; i++) {
            int ct = ctb + 2 * i;
            FragC acc; wmma::fill_fragment(acc, 0.f);
#pragma unroll
            for (int k = 0; k < 24; k++) {
                FragA af; wmma::load_matrix_sync(af, as + rt * 16 * XS_LD + k * 8, XS_LD);
                FragB bf; wmma::load_matrix_sync(bf, g_fc1w_t + (size_t)k * 8 * 768 + chunk * 192 + ct * 16, 768);
                wmma::mma_sync(acc, af, bf, acc);
            }
            wmma::store_matrix_sync(mid + rt * 16 * XS_LD + ct * 16, acc, XS_LD, wmma::mem_row_major);
        }
        __syncthreads();

        // bias + exact GELU + tf32 round, in place
        for (int idx = tid; idx < 64 * 192; idx += 256) {
            int r = idx / 192, c = idx - r * 192;
            float v = mid[r * XS_LD + c] + fc1b[chunk * 192 + c];
            mid[r * XS_LD + c] = tf32r(0.5f * v * (1.f + erff(v * 0.70710678118654752f)));
        }
        __syncthreads();

        // GEMM2 partial: [64,192] x [192,192], register accumulate
#pragma unroll
        for (int kk = 0; kk < 24; kk++) {
            FragA af; wmma::load_matrix_sync(af, mid + rt * 16 * XS_LD + kk * 8, XS_LD);
#pragma unroll
            for (int j = 0; j < 6; j++) {
                int ct = ctb + 2 * j;
                FragB bf; wmma::load_matrix_sync(bf, g_fc2w_t + (size_t)(chunk * 192 + kk * 8) * 192 + ct * 16, 192);
                wmma::mma_sync(acc2[j], af, bf, acc2[j]);
            }
        }
        __syncthreads();
    }

    // store MLP output
#pragma unroll
    for (int j = 0; j < 6; j++) {
        int ct = ctb + 2 * j;
        wmma::store_matrix_sync(mid + rt * 16 * XS_LD + ct * 16, acc2[j], XS_LD, wmma::mem_row_major);
    }
    __syncthreads();

    // residual + bias
    for (int idx = tid; idx < 64 * 192; idx += 256) {
        int r = idx / 192, c = idx - r * 192;
        mid[r * XS_LD + c] += g_h1[(size_t)(t0 + r) * 192 + c] + fc2b[c];
    }
    __syncthreads();

    // scatter to NCHW
    for (int idx = tid; idx < 64 * 192; idx += 256) {
        int r = idx & 63;
        int c = idx >> 6;
        int t = t0 + r;
        int win = t / 49; int pos = t - win * 49;
        int b  = win >> 10;
        int wh = (win >> 5) & 31;
        int ww = win & 31;
        int pi = pos / 7;
        int hh = wh * 7 + pi;
        int wx = ww * 7 + (pos - pi * 7);
        out[((size_t)(b * DIMC + c)) * HWSQ + hh * HWI + wx] = mid[r * XS_LD + c];
    }
}

// ============================================================================
extern "C" void kernel_launch(void* const* d_in, const int* in_sizes, int n_in,
                              void* d_out, int out_size)
{
    (void)in_sizes; (void)n_in; (void)out_size;
    const float* x     = (const float*)d_in[0];
    const float* ln1w  = (const float*)d_in[1];
    const float* ln1b  = (const float*)d_in[2];
    const float* qkvw  = (const float*)d_in[3];
    const float* qkvb  = (const float*)d_in[4];
    const float* projw = (const float*)d_in[5];
    const float* projb = (const float*)d_in[6];
    const float* rpb   = (const float*)d_in[7];
    const float* ln2w  = (const float*)d_in[8];
    const float* ln2b  = (const float*)d_in[9];
    const float* fc1w  = (const float*)d_in[10];
    const float* fc1b  = (const float*)d_in[11];
    const float* fc2w  = (const float*)d_in[12];
    const float* fc2b  = (const float*)d_in[13];
    const int*   ridx  = (const int*)  d_in[14];
    float* out = (float*)d_out;

    cudaFuncSetAttribute(attn_kernel, cudaFuncAttributeMaxDynamicSharedMemorySize, ATTN_SMEM);
    cudaFuncSetAttribute(mlp_kernel,  cudaFuncAttributeMaxDynamicSharedMemorySize, MLP_SMEM);

    prelude<<<(PRE_TOT + 511) / 512, 512>>>(qkvw, projw, fc1w, fc2w, rpb, ridx);

    attn_kernel<<<NWIN, 512, ATTN_SMEM>>>(x, ln1w, ln1b, qkvb, projb, ln2w, ln2b);

    mlp_kernel<<<TTOK / 64, 256, MLP_SMEM>>>(fc1b, fc2b, out);
}

// round 4
// speedup vs baseline: 2.0743x; 2.0743x over previous
#include <cuda_runtime.h>
#include <cuda_bf16.h>
#include <mma.h>
#include <cmath>

using namespace nvcuda;
typedef __nv_bfloat16 bf16;

// ---------------- problem constants ----------------
#define NWIN   8192
#define TTOK   401408
#define HWI    224
#define HWSQ   50176
#define DIMC   192

__device__ __forceinline__ float tf32r(float v) {
    float r;
    asm("cvt.rna.tf32.f32 %0, %1;" : "=f"(r) : "f"(v));
    return r;
}

// scratch (allocation-free static device arrays)
__device__ float g_h1  [(size_t)TTOK * DIMC];   // x + attn branch (fp32)
__device__ bf16  g_h1n [(size_t)TTOK * DIMC];   // LN2(h1) in bf16 (MLP input)
__device__ float g_qkvw_t[192 * 576];           // tf32-rounded
__device__ float g_projw_t[192 * 192];          // tf32-rounded
__device__ bf16  g_fc1w_b [192 * 768];          // bf16
__device__ bf16  g_fc2w_b [768 * 192];          // bf16
__device__ float g_bias   [6 * 49 * 49];        // rpb[relidx[r,j]*6+h]

// tf32 fragments (attention path)
typedef wmma::fragment<wmma::matrix_a,16,16,8,wmma::precision::tf32,wmma::row_major> FragA;
typedef wmma::fragment<wmma::matrix_b,16,16,8,wmma::precision::tf32,wmma::row_major> FragB;
typedef wmma::fragment<wmma::matrix_b,16,16,8,wmma::precision::tf32,wmma::col_major> FragBT;
typedef wmma::fragment<wmma::accumulator,16,16,8,float> FragC;
// bf16 fragments (MLP path)
typedef wmma::fragment<wmma::matrix_a,16,16,16,bf16,wmma::row_major> FragAb;
typedef wmma::fragment<wmma::matrix_b,16,16,16,bf16,wmma::row_major> FragBb;
typedef wmma::fragment<wmma::accumulator,16,16,16,float> FragCb;

// ---------------- prelude ----------------
#define W_QKV 110592
#define W_PRJ  36864
#define W_FC1 147456
#define W_FC2 147456
#define N_BIAS 14406
#define PRE_TOT (W_QKV + W_PRJ + W_FC1 + W_FC2 + N_BIAS)

__global__ void prelude(const float* __restrict__ qkvw, const float* __restrict__ projw,
                        const float* __restrict__ fc1w, const float* __restrict__ fc2w,
                        const float* __restrict__ rpb,  const int* __restrict__ relidx)
{
    int i = blockIdx.x * blockDim.x + threadIdx.x;
    if (i < W_QKV) { g_qkvw_t[i] = tf32r(qkvw[i]); return; }
    i -= W_QKV;
    if (i < W_PRJ) { g_projw_t[i] = tf32r(projw[i]); return; }
    i -= W_PRJ;
    if (i < W_FC1) { g_fc1w_b[i] = __float2bfloat16(fc1w[i]); return; }
    i -= W_FC1;
    if (i < W_FC2) { g_fc2w_b[i] = __float2bfloat16(fc2w[i]); return; }
    i -= W_FC2;
    if (i < N_BIAS) {
        int h = i / 2401, rj = i - h * 2401;
        g_bias[i] = rpb[relidx[rj] * 6 + h];
    }
}

// ============================================================================
// Kernel 1: per-window (512 threads, 16 warps), tf32 numerics as round 1/3.
// smem floats: xs[64][196]@0  qkv[64][580]@12544  sc[64][68]@49664
// ============================================================================
#define XS_LD 196
#define QK_LD 580
#define SC_LD 68
#define ATTN_SMEM 216064

__global__ void __launch_bounds__(512, 1)
attn_kernel(const float* __restrict__ x,
            const float* __restrict__ ln1w, const float* __restrict__ ln1b,
            const float* __restrict__ qkvb,
            const float* __restrict__ projb,
            const float* __restrict__ ln2w, const float* __restrict__ ln2b)
{
    extern __shared__ float sm[];
    float* xs  = sm;
    float* qkv = sm + 12544;
    float* sc  = sm + 49664;

    const int tid  = threadIdx.x;
    const int wid  = tid >> 5;
    const int lane = tid & 31;

    const int win = blockIdx.x;
    const int b   = win >> 10;
    const int wh  = (win >> 5) & 31;
    const int ww  = win & 31;
    const float* xb = x + (size_t)b * DIMC * HWSQ;

    for (int i = 49 * XS_LD + tid; i < 64 * XS_LD; i += 512) xs[i] = 0.f;
    for (int idx = tid; idx < DIMC * 49; idx += 512) {
        int c = idx / 49, r = idx - c * 49;
        int i = r / 7, j = r - i * 7;
        xs[r * XS_LD + c] = xb[(size_t)c * HWSQ + (wh * 7 + i) * HWI + (ww * 7 + j)];
    }
    __syncthreads();

    // LN1 -> tf32-rounded
    for (int r = wid; r < 49; r += 16) {
        float v[6]; float s = 0.f;
#pragma unroll
        for (int q = 0; q < 6; q++) { v[q] = xs[r * XS_LD + lane + q * 32]; s += v[q]; }
#pragma unroll
        for (int o = 16; o; o >>= 1) s += __shfl_xor_sync(~0u, s, o);
        float mu = s * (1.f / 192.f);
        float vs = 0.f;
#pragma unroll
        for (int q = 0; q < 6; q++) { float d = v[q] - mu; vs += d * d; }
#pragma unroll
        for (int o = 16; o; o >>= 1) vs += __shfl_xor_sync(~0u, vs, o);
        float rs = rsqrtf(vs * (1.f / 192.f) + 1e-5f);
#pragma unroll
        for (int q = 0; q < 6; q++) {
            int c = lane + q * 32;
            xs[r * XS_LD + c] = tf32r((v[q] - mu) * rs * ln1w[c] + ln1b[c]);
        }
    }
    __syncthreads();

    // ---- QKV GEMM: k-outer, 9 accumulators (A amortized 9x) ----
    {
        const int rt = wid & 3, ctb = wid >> 2;
        FragC acc[9];
#pragma unroll
        for (int j = 0; j < 9; j++) wmma::fill_fragment(acc[j], 0.f);
        for (int k = 0; k < 24; k++) {
            FragA af; wmma::load_matrix_sync(af, xs + rt * 16 * XS_LD + k * 8, XS_LD);
#pragma unroll
            for (int j = 0; j < 9; j++) {
                FragB bf;
                wmma::load_matrix_sync(bf, g_qkvw_t + (size_t)k * 8 * 576 + (ctb + 4 * j) * 16, 576);
                wmma::mma_sync(acc[j], af, bf, acc[j]);
            }
        }
#pragma unroll
        for (int j = 0; j < 9; j++)
            wmma::store_matrix_sync(qkv + rt * 16 * QK_LD + (ctb + 4 * j) * 16, acc[j], QK_LD, wmma::mem_row_major);
    }
    __syncthreads();
    // epilogue: bias, scale q, tf32-round (rows<49; pad rows stay 0)
    const float scale = 0.17677669529663687f;
    for (int idx = tid; idx < 49 * 576; idx += 512) {
        int r = idx / 576, c = idx - r * 576;
        float v = qkv[r * QK_LD + c] + qkvb[c];
        if (c < 192) v *= scale;
        qkv[r * QK_LD + c] = tf32r(v);
    }
    __syncthreads();

    // ---- attention: one head per iteration ----
    for (int h = 0; h < 6; h++) {
        {   // scores: 16 tiles, one per warp
            int rt = wid >> 2, ct = wid & 3;
            FragC acc; wmma::fill_fragment(acc, 0.f);
#pragma unroll
            for (int k = 0; k < 4; k++) {
                FragA af; wmma::load_matrix_sync(af, qkv + rt * 16 * QK_LD + h * 32 + k * 8, QK_LD);
                FragBT bf; wmma::load_matrix_sync(bf, qkv + ct * 16 * QK_LD + 192 + h * 32 + k * 8, QK_LD);
                wmma::mma_sync(acc, af, bf, acc);
            }
            wmma::store_matrix_sync(sc + rt * 16 * SC_LD + ct * 16, acc, SC_LD, wmma::mem_row_major);
        }
        __syncthreads();

        const float* bh = g_bias + h * 2401;
        for (int r = wid; r < 49; r += 16) {
            float* srow = sc + r * SC_LD;
            int j0 = lane, j1 = lane + 32;
            float v0 = srow[j0] + bh[r * 49 + j0];
            float v1 = (j1 < 49) ? srow[j1] + bh[r * 49 + j1] : -1e30f;
            float m = fmaxf(v0, v1);
#pragma unroll
            for (int o = 16; o; o >>= 1) m = fmaxf(m, __shfl_xor_sync(~0u, m, o));
            float e0 = expf(v0 - m);
            float e1 = (j1 < 49) ? expf(v1 - m) : 0.f;
            float s = e0 + e1;
#pragma unroll
            for (int o = 16; o; o >>= 1) s += __shfl_xor_sync(~0u, s, o);
            float inv = 1.f / s;
            srow[j0] = tf32r(e0 * inv);
            if (j1 < 49) srow[j1] = tf32r(e1 * inv);
        }
        __syncthreads();

        if (wid < 8) { // PV: 8 tiles
            int rt = wid >> 1, ct = wid & 1;
            FragC acc; wmma::fill_fragment(acc, 0.f);
#pragma unroll
            for (int k = 0; k < 8; k++) {
                FragA af; wmma::load_matrix_sync(af, sc + rt * 16 * SC_LD + k * 8, SC_LD);
                FragB bf; wmma::load_matrix_sync(bf, qkv + (size_t)k * 8 * QK_LD + 384 + h * 32 + ct * 16, QK_LD);
                wmma::mma_sync(acc, af, bf, acc);
            }
            wmma::store_matrix_sync(xs + rt * 16 * XS_LD + h * 32 + ct * 16, acc, XS_LD, wmma::mem_row_major);
        }
        __syncthreads();
    }

    // tf32-round attn output (proj A operand)
    for (int idx = tid; idx < 49 * 192; idx += 512) {
        int r = idx / 192, c = idx - r * 192;
        xs[r * XS_LD + c] = tf32r(xs[r * XS_LD + c]);
    }
    __syncthreads();

    // ---- proj GEMM: k-outer, 3 accumulators ----
    {
        const int rt = wid & 3, ctb = wid >> 2;
        FragC acc[3];
#pragma unroll
        for (int j = 0; j < 3; j++) wmma::fill_fragment(acc[j], 0.f);
        for (int k = 0; k < 24; k++) {
            FragA af; wmma::load_matrix_sync(af, xs + rt * 16 * XS_LD + k * 8, XS_LD);
#pragma unroll
            for (int j = 0; j < 3; j++) {
                FragB bf;
                wmma::load_matrix_sync(bf, g_projw_t + (size_t)k * 8 * 192 + (ctb + 4 * j) * 16, 192);
                wmma::mma_sync(acc[j], af, bf, acc[j]);
            }
        }
#pragma unroll
        for (int j = 0; j < 3; j++)
            wmma::store_matrix_sync(qkv + rt * 16 * XS_LD + (ctb + 4 * j) * 16, acc[j], XS_LD, wmma::mem_row_major);
    }
    __syncthreads();

    // residual: qkv(ld XS_LD) += x + projb
    for (int idx = tid; idx < DIMC * 49; idx += 512) {
        int c = idx / 49, r = idx - c * 49;
        int i = r / 7, j = r - i * 7;
        float xv = xb[(size_t)c * HWSQ + (wh * 7 + i) * HWI + (ww * 7 + j)];
        qkv[r * XS_LD + c] += xv + projb[c];
    }
    __syncthreads();

    // LN2 + write h1 (fp32) / h1n (bf16)
    size_t base = (size_t)win * 49 * DIMC;
    for (int r = wid; r < 49; r += 16) {
        float v[6]; float s = 0.f;
#pragma unroll
        for (int q = 0; q < 6; q++) { v[q] = qkv[r * XS_LD + lane + q * 32]; s += v[q]; }
#pragma unroll
        for (int o = 16; o; o >>= 1) s += __shfl_xor_sync(~0u, s, o);
        float mu = s * (1.f / 192.f);
        float vs = 0.f;
#pragma unroll
        for (int q = 0; q < 6; q++) { float d = v[q] - mu; vs += d * d; }
#pragma unroll
        for (int o = 16; o; o >>= 1) vs += __shfl_xor_sync(~0u, vs, o);
        float rs = rsqrtf(vs * (1.f / 192.f) + 1e-5f);
#pragma unroll
        for (int q = 0; q < 6; q++) {
            int c = lane + q * 32;
            g_h1 [base + r * DIMC + c] = v[q];
            g_h1n[base + r * DIMC + c] = __float2bfloat16((v[q] - mu) * rs * ln2w[c] + ln2b[c]);
        }
    }
}

// ============================================================================
// Kernel 2 (256 threads, 2 CTAs/SM): bf16 MLP, 4 K-chunks of 192, GEMM2
// register-accumulated across chunks.
// smem: as bf16[64][200]@0 (25600B); mid f32[64][196]@25600 (50176B);
//       midb bf16[64][200]@75776 (25600B); total 101376
// ============================================================================
#define AS_LD 200
#define MD_LD 196
#define MLP_SMEM 101376

__global__ void __launch_bounds__(256, 2)
mlp_kernel(const float* __restrict__ fc1b, const float* __restrict__ fc2b,
           float* __restrict__ out)
{
    extern __shared__ char smc[];
    bf16*  as   = (bf16*)smc;
    float* mid  = (float*)(smc + 25600);
    bf16*  midb = (bf16*)(smc + 75776);

    const int tid = threadIdx.x;
    const int wid = tid >> 5;
    const int t0  = blockIdx.x * 64;
    const int rt  = wid & 3;
    const int ctb = wid >> 2;   // 0 or 1

    // load h1n tile (uint4 = 8 bf16, coalesced)
    {
        const uint4* src = (const uint4*)g_h1n;
        uint4* dst = (uint4*)as;
        for (int idx = tid; idx < 64 * 24; idx += 256) {
            int r = idx / 24, c = idx - r * 24;
            dst[r * 25 + c] = src[(size_t)(t0 + r) * 24 + c];
        }
    }
    __syncthreads();

    FragCb acc2[6];
#pragma unroll
    for (int j = 0; j < 6; j++) wmma::fill_fragment(acc2[j], 0.f);

    for (int chunk = 0; chunk < 4; chunk++) {
        // GEMM1: [64,192]x[192,192] bf16, two groups of 3 accumulators
#pragma unroll
        for (int g = 0; g < 2; g++) {
            FragCb acc[3];
#pragma unroll
            for (int j = 0; j < 3; j++) wmma::fill_fragment(acc[j], 0.f);
            for (int k = 0; k < 12; k++) {
                FragAb af; wmma::load_matrix_sync(af, as + rt * 16 * AS_LD + k * 16, AS_LD);
#pragma unroll
                for (int j = 0; j < 3; j++) {
                    int ct = ctb + 2 * (3 * g + j);
                    FragBb bf;
                    wmma::load_matrix_sync(bf, g_fc1w_b + (size_t)k * 16 * 768 + chunk * 192 + ct * 16, 768);
                    wmma::mma_sync(acc[j], af, bf, acc[j]);
                }
            }
#pragma unroll
            for (int j = 0; j < 3; j++) {
                int ct = ctb + 2 * (3 * g + j);
                wmma::store_matrix_sync(mid + rt * 16 * MD_LD + ct * 16, acc[j], MD_LD, wmma::mem_row_major);
            }
        }
        __syncthreads();

        // bias + exact GELU -> midb bf16
        for (int idx = tid; idx < 64 * 192; idx += 256) {
            int r = idx / 192, c = idx - r * 192;
            float v = mid[r * MD_LD + c] + fc1b[chunk * 192 + c];
            midb[r * AS_LD + c] = __float2bfloat16(0.5f * v * (1.f + erff(v * 0.70710678118654752f)));
        }
        __syncthreads();

        // GEMM2 partial: register accumulate across chunks
        for (int kk = 0; kk < 12; kk++) {
            FragAb af; wmma::load_matrix_sync(af, midb + rt * 16 * AS_LD + kk * 16, AS_LD);
#pragma unroll
            for (int j = 0; j < 6; j++) {
                int ct = ctb + 2 * j;
                FragBb bf;
                wmma::load_matrix_sync(bf, g_fc2w_b + (size_t)(chunk * 192 + kk * 16) * 192 + ct * 16, 192);
                wmma::mma_sync(acc2[j], af, bf, acc2[j]);
            }
        }
        __syncthreads();
    }

    // store MLP output to mid
#pragma unroll
    for (int j = 0; j < 6; j++) {
        int ct = ctb + 2 * j;
        wmma::store_matrix_sync(mid + rt * 16 * MD_LD + ct * 16, acc2[j], MD_LD, wmma::mem_row_major);
    }
    __syncthreads();

    // residual + bias + scatter to NCHW (single pass)
    for (int idx = tid; idx < 64 * 192; idx += 256) {
        int r = idx & 63;
        int c = idx >> 6;
        int t = t0 + r;
        int win = t / 49; int pos = t - win * 49;
        int b  = win >> 10;
        int wh = (win >> 5) & 31;
        int ww = win & 31;
        int pi = pos / 7;
        int hh = wh * 7 + pi;
        int wx = ww * 7 + (pos - pi * 7);
        out[((size_t)(b * DIMC + c)) * HWSQ + hh * HWI + wx] =
            mid[r * MD_LD + c] + g_h1[(size_t)t * 192 + c] + fc2b[c];
    }
}

// ============================================================================
extern "C" void kernel_launch(void* const* d_in, const int* in_sizes, int n_in,
                              void* d_out, int out_size)
{
    (void)in_sizes; (void)n_in; (void)out_size;
    const float* x     = (const float*)d_in[0];
    const float* ln1w  = (const float*)d_in[1];
    const float* ln1b  = (const float*)d_in[2];
    const float* qkvw  = (const float*)d_in[3];
    const float* qkvb  = (const float*)d_in[4];
    const float* projw = (const float*)d_in[5];
    const float* projb = (const float*)d_in[6];
    const float* rpb   = (const float*)d_in[7];
    const float* ln2w  = (const float*)d_in[8];
    const float* ln2b  = (const float*)d_in[9];
    const float* fc1w  = (const float*)d_in[10];
    const float* fc1b  = (const float*)d_in[11];
    const float* fc2w  = (const float*)d_in[12];
    const float* fc2b  = (const float*)d_in[13];
    const int*   ridx  = (const int*)  d_in[14];
    float* out = (float*)d_out;

    cudaFuncSetAttribute(attn_kernel, cudaFuncAttributeMaxDynamicSharedMemorySize, ATTN_SMEM);
    cudaFuncSetAttribute(mlp_kernel,  cudaFuncAttributeMaxDynamicSharedMemorySize, MLP_SMEM);

    prelude<<<(PRE_TOT + 511) / 512, 512>>>(qkvw, projw, fc1w, fc2w, rpb, ridx);

    attn_kernel<<<NWIN, 512, ATTN_SMEM>>>(x, ln1w, ln1b, qkvb, projb, ln2w, ln2b);

    mlp_kernel<<<TTOK / 64, 256, MLP_SMEM>>>(fc1b, fc2b, out);
}